// round 15
// baseline (speedup 1.0000x reference)
#include <cuda_runtime.h>
#include <cstdint>

// Problem constants (B=4, S=1024, K=32, V=32000)
#define BB 4
#define SS 1024
#define KK 32
#define VV 32000
#define ROWS (BB * SS)          // 4096
#define CHUNK 4096              // floats per block (256 threads * 4 * float4)
#define NCHUNK ((VV + CHUNK - 1) / CHUNK)   // 8 (last chunk = 3328 floats)

// Scratch (device global — no allocation). Packed deduped scatter list:
// .x = target index (or -1 for dropped duplicate lanes), .y = float bits of p.
__device__ int2 g_scat[ROWS * KK];

__device__ __forceinline__ float fast_tanh(float x) {
    float r;
    asm("tanh.approx.f32 %0, %1;" : "=f"(r) : "f"(x));
    return r;
}

// ---------------------------------------------------------------------------
// Kernel A (~4.2us): one warp per row, 8 rows/block (512 blocks, one wave).
// Fast chain: label counts via match_any+ballot+popc; fc2 feats staged in
// smem; in-warp duplicate-target combine so kernel B can use plain stores.
// ---------------------------------------------------------------------------
__global__ void __launch_bounds__(256) compute_kernel(
    const int*   __restrict__ tgt,
    const float* __restrict__ dists,
    const float* __restrict__ kkf,
    const float* __restrict__ nsp,
    const float* __restrict__ fc1_w1,  // (2,4)
    const float* __restrict__ fc1_b1,  // (4)
    const float* __restrict__ fc1_w2,  // (4,1)
    const float* __restrict__ fc1_b2,  // (1)
    const float* __restrict__ fc2_w1,  // (64,32)
    const float* __restrict__ fc2_b1,  // (32)
    const float* __restrict__ fc2_w2,  // (32,2)
    const float* __restrict__ fc2_b2)  // (2)
{
    const unsigned FULL = 0xffffffffu;
    __shared__ float feat[8][64];
    __shared__ float sp  [8][32];

    const int w    = threadIdx.x >> 5;
    const int lane = threadIdx.x & 31;
    const int row  = blockIdx.x * 8 + w;
    const int base = row * KK + lane;

    int   t   = tgt[base];
    float d   = dists[base];
    float lkf = __logf(kkf[base]);
    float lsp = __logf(nsp[base]);

    // label_counts: distinct nonzero labels in prefix [0..lane]
    unsigned mgrp = __match_any_sync(FULL, t);
    int leader = __ffs(mgrp) - 1;
    bool fo = (t != 0) && (leader == lane);
    unsigned fomask = __ballot_sync(FULL, fo);
    float lc = (float)__popc(fomask & (0xFFFFFFFFu >> (31 - lane)));

    // fc1 -> noise_logit
    float noise = fc1_b2[0];
    #pragma unroll
    for (int m = 0; m < 4; m++) {
        float h = fmaf(lkf, fc1_w1[m], fmaf(lsp, fc1_w1[4 + m], fc1_b1[m]));
        noise = fmaf(fast_tanh(h), fc1_w2[m], noise);
    }

    // stage feats, then fc2: hidden[lane] = b1 + sum_j feat[j]*W1[j][lane]
    feat[w][lane]      = d;
    feat[w][32 + lane] = lc;
    __syncwarp();
    float hid = fc2_b1[lane];
    #pragma unroll
    for (int j = 0; j < 64; j++) {
        hid = fmaf(feat[w][j], fc2_w1[j * 32 + lane], hid);
    }
    float ht = fast_tanh(hid);

    // lambda_logit[1] -> tempe
    float l1 = ht * fc2_w2[lane * 2 + 1];
    #pragma unroll
    for (int off = 16; off; off >>= 1) l1 += __shfl_xor_sync(FULL, l1, off);
    l1 += fc2_b2[1];
    float tempe = 1.f / (1.f + __expf(-l1));

    // softmax over K of (-d*tempe + noise)
    float logit = fmaf(-d, tempe, noise);
    float mx = logit;
    #pragma unroll
    for (int off = 16; off; off >>= 1) mx = fmaxf(mx, __shfl_xor_sync(FULL, mx, off));
    float e = __expf(logit - mx);
    float s = e;
    #pragma unroll
    for (int off = 16; off; off >>= 1) s += __shfl_xor_sync(FULL, s, off);
    float p = e / s;

    // in-warp duplicate-target combine (group-sum via smem)
    sp[w][lane] = p;
    __syncwarp();
    float psum = p;
    unsigned m = mgrp & ~(1u << lane);
    while (m) { int j = __ffs(m) - 1; psum += sp[w][j]; m &= m - 1; }

    g_scat[base] = make_int2((leader == lane) ? t : -1, __float_as_int(psum));
}

// ---------------------------------------------------------------------------
// Kernel B: zero + inline scatter. CHUNK=4096: four independent float4
// stores per thread, quartering the R13 block count (32768 blocks) and the
// per-block overheads (launch, prefetch LDG, barrier).
// ---------------------------------------------------------------------------
__global__ void __launch_bounds__(256) zero_scatter_kernel(
    float* __restrict__ out)
{
    const int row   = blockIdx.y;
    const int chunk = blockIdx.x;
    const int tid   = threadIdx.x;

    const int lo = chunk * CHUNK;
    const int n  = min(CHUNK, VV - lo);         // 4096, or 3328 for last chunk
    float* rowp = out + (size_t)row * VV + lo;

    // prefetch the packed scatter entry (warp 0) before the stores
    int2 sc = make_int2(-1, 0);
    if (tid < 32) sc = g_scat[row * KK + tid];

    // zero this chunk: four independent float4 stores per thread
    const float4 z = make_float4(0.f, 0.f, 0.f, 0.f);
    int i4 = tid * 4;
    #pragma unroll
    for (int k = 0; k < 4; k++) {
        int off = i4 + k * 1024;
        if (off < n) *(float4*)(rowp + off) = z;
    }

    __syncthreads();  // order zero-stores before the targeted stores

    if (tid < 32) {
        int loc = sc.x - lo;
        if (loc >= 0 && loc < n) rowp[loc] = __int_as_float(sc.y);
    }
}

// metadata order:
//  0 tgt_index(i32) 1 knn_dists 2 knn_key_feature 3 network_probs(UNUSED)
//  4 network_select_probs 5 dfc_w(UNUSED) 6 dfc_b(UNUSED)
//  7 fc1_w1 8 fc1_b1 9 fc1_w2 10 fc1_b2 11 fc2_w1 12 fc2_b1 13 fc2_w2 14 fc2_b2
extern "C" void kernel_launch(void* const* d_in, const int* in_sizes, int n_in,
                              void* d_out, int out_size) {
    const int*   tgt    = (const int*)  d_in[0];
    const float* dists  = (const float*)d_in[1];
    const float* kkf    = (const float*)d_in[2];
    const float* nsp    = (const float*)d_in[4];
    const float* fc1_w1 = (const float*)d_in[7];
    const float* fc1_b1 = (const float*)d_in[8];
    const float* fc1_w2 = (const float*)d_in[9];
    const float* fc1_b2 = (const float*)d_in[10];
    const float* fc2_w1 = (const float*)d_in[11];
    const float* fc2_b1 = (const float*)d_in[12];
    const float* fc2_w2 = (const float*)d_in[13];
    const float* fc2_b2 = (const float*)d_in[14];
    float* out = (float*)d_out;

    // A: 4096 rows, 8 rows/block -> 512 blocks (one wave)
    compute_kernel<<<ROWS / 8, 256>>>(tgt, dists, kkf, nsp,
                                      fc1_w1, fc1_b1, fc1_w2, fc1_b2,
                                      fc2_w1, fc2_b1, fc2_w2, fc2_b2);

    // B: flat zero+scatter, grid (8 chunks, 4096 rows)
    dim3 grid(NCHUNK, ROWS);
    zero_scatter_kernel<<<grid, 256>>>(out);
}

// round 16
// speedup vs baseline: 1.0051x; 1.0051x over previous
#include <cuda_runtime.h>
#include <cstdint>

// Problem constants (B=4, S=1024, K=32, V=32000)
#define BB 4
#define SS 1024
#define KK 32
#define VV 32000
#define ROWS (BB * SS)          // 4096
#define HEAD 2048               // floats of each row zeroed by the compute kernel
#define CHUNK 2048              // floats per consumer block
#define NCHUNK 15               // chunks covering [HEAD, VV): 14*2048 + 1280

// Scratch (device global — no allocation). Packed deduped scatter list:
// .x = target index (or -1 for dropped duplicate lanes), .y = float bits of p.
__device__ int2 g_scat[ROWS * KK];

__device__ __forceinline__ float fast_tanh(float x) {
    float r;
    asm("tanh.approx.f32 %0, %1;" : "=f"(r) : "f"(x));
    return r;
}

// ---------------------------------------------------------------------------
// Kernel A: one warp per row, 8 rows/block (512 blocks, one wave).
// Each warp:
//   1) issues 16 fire-and-forget float4 stores zeroing row[0..HEAD)
//   2) runs the combiner chain (stores drain in the background):
//      label_counts (match_any) -> fc2 -> tempe ; log feats -> fc1 -> noise ;
//      p = softmax(-d*tempe + noise); in-warp duplicate-target combine
//   3) __syncwarp, then inline-scatters targets < HEAD into its own row
//   4) publishes the packed scatter list for the consumer (targets >= HEAD)
// ---------------------------------------------------------------------------
__global__ void __launch_bounds__(256) compute_kernel(
    const int*   __restrict__ tgt,
    const float* __restrict__ dists,
    const float* __restrict__ kkf,
    const float* __restrict__ nsp,
    const float* __restrict__ fc1_w1,  // (2,4)
    const float* __restrict__ fc1_b1,  // (4)
    const float* __restrict__ fc1_w2,  // (4,1)
    const float* __restrict__ fc1_b2,  // (1)
    const float* __restrict__ fc2_w1,  // (64,32)
    const float* __restrict__ fc2_b1,  // (32)
    const float* __restrict__ fc2_w2,  // (32,2)
    const float* __restrict__ fc2_b2,  // (2)
    float*       __restrict__ out)     // (ROWS, VV)
{
    const unsigned FULL = 0xffffffffu;
    __shared__ float feat[8][64];
    __shared__ float sp  [8][32];

    const int w    = threadIdx.x >> 5;
    const int lane = threadIdx.x & 31;
    const int row  = blockIdx.x * 8 + w;
    const int base = row * KK + lane;
    float* rowp = out + (size_t)row * VV;

    // ---- 1) zero row[0..HEAD): 16 independent float4 stores per lane ------
    {
        const float4 z = make_float4(0.f, 0.f, 0.f, 0.f);
        #pragma unroll
        for (int k = 0; k < HEAD / 128; k++) {        // 16 iterations
            *(float4*)(rowp + k * 128 + lane * 4) = z;
        }
    }

    // ---- 2) combiner chain (overlaps the store drain) ----------------------
    int   t   = tgt[base];
    float d   = dists[base];
    float lkf = __logf(kkf[base]);
    float lsp = __logf(nsp[base]);

    // label_counts: distinct nonzero labels in prefix [0..lane]
    unsigned mgrp = __match_any_sync(FULL, t);
    int leader = __ffs(mgrp) - 1;
    bool fo = (t != 0) && (leader == lane);
    unsigned fomask = __ballot_sync(FULL, fo);
    float lc = (float)__popc(fomask & (0xFFFFFFFFu >> (31 - lane)));

    // fc1 -> noise_logit
    float noise = fc1_b2[0];
    #pragma unroll
    for (int m = 0; m < 4; m++) {
        float h = fmaf(lkf, fc1_w1[m], fmaf(lsp, fc1_w1[4 + m], fc1_b1[m]));
        noise = fmaf(fast_tanh(h), fc1_w2[m], noise);
    }

    // stage feats, then fc2: hidden[lane] = b1 + sum_j feat[j]*W1[j][lane]
    feat[w][lane]      = d;
    feat[w][32 + lane] = lc;
    __syncwarp();
    float hid = fc2_b1[lane];
    #pragma unroll
    for (int j = 0; j < 64; j++) {
        hid = fmaf(feat[w][j], fc2_w1[j * 32 + lane], hid);
    }
    float ht = fast_tanh(hid);

    // lambda_logit[1] -> tempe
    float l1 = ht * fc2_w2[lane * 2 + 1];
    #pragma unroll
    for (int off = 16; off; off >>= 1) l1 += __shfl_xor_sync(FULL, l1, off);
    l1 += fc2_b2[1];
    float tempe = 1.f / (1.f + __expf(-l1));

    // softmax over K of (-d*tempe + noise)
    float logit = fmaf(-d, tempe, noise);
    float mx = logit;
    #pragma unroll
    for (int off = 16; off; off >>= 1) mx = fmaxf(mx, __shfl_xor_sync(FULL, mx, off));
    float e = __expf(logit - mx);
    float s = e;
    #pragma unroll
    for (int off = 16; off; off >>= 1) s += __shfl_xor_sync(FULL, s, off);
    float p = e / s;

    // in-warp duplicate-target combine (group-sum via smem)
    sp[w][lane] = p;
    __syncwarp();
    float psum = p;
    unsigned m = mgrp & ~(1u << lane);
    while (m) { int j = __ffs(m) - 1; psum += sp[w][j]; m &= m - 1; }
    int tkeep = (leader == lane) ? t : -1;

    // ---- 3) inline scatter for targets in [0, HEAD) ------------------------
    __syncwarp();   // order this warp's zero stores before the scatter store
    if (tkeep >= 0 && tkeep < HEAD) rowp[tkeep] = psum;

    // ---- 4) publish for the consumer (targets >= HEAD match there) --------
    g_scat[base] = make_int2(tkeep, __float_as_int(psum));
}

// ---------------------------------------------------------------------------
// Kernel B: zero + inline scatter over [HEAD, VV) — R14 proven shape.
// Grid (15, 4096); each thread two independent float4 stores; warp 0
// prefetches the packed scatter list and plain-stores hits after the barrier.
// ---------------------------------------------------------------------------
__global__ void __launch_bounds__(256) zero_scatter_kernel(
    float* __restrict__ out)
{
    const int row   = blockIdx.y;
    const int chunk = blockIdx.x;
    const int tid   = threadIdx.x;

    const int lo = HEAD + chunk * CHUNK;
    const int n  = min(CHUNK, VV - lo);         // 2048, or 1280 for last chunk
    float* rowp = out + (size_t)row * VV + lo;

    // prefetch the packed scatter entry (warp 0) before the stores
    int2 sc = make_int2(-1, 0);
    if (tid < 32) sc = g_scat[row * KK + tid];

    // zero this chunk: two independent float4 stores per thread
    const float4 z = make_float4(0.f, 0.f, 0.f, 0.f);
    int i4 = tid * 4;
    if (i4 < n)        *(float4*)(rowp + i4)        = z;
    if (i4 + 1024 < n) *(float4*)(rowp + i4 + 1024) = z;

    __syncthreads();  // order zero-stores before the targeted stores

    if (tid < 32) {
        int loc = sc.x - lo;                    // sc.x < HEAD never matches
        if (loc >= 0 && loc < n) rowp[loc] = __int_as_float(sc.y);
    }
}

// metadata order:
//  0 tgt_index(i32) 1 knn_dists 2 knn_key_feature 3 network_probs(UNUSED)
//  4 network_select_probs 5 dfc_w(UNUSED) 6 dfc_b(UNUSED)
//  7 fc1_w1 8 fc1_b1 9 fc1_w2 10 fc1_b2 11 fc2_w1 12 fc2_b1 13 fc2_w2 14 fc2_b2
extern "C" void kernel_launch(void* const* d_in, const int* in_sizes, int n_in,
                              void* d_out, int out_size) {
    const int*   tgt    = (const int*)  d_in[0];
    const float* dists  = (const float*)d_in[1];
    const float* kkf    = (const float*)d_in[2];
    const float* nsp    = (const float*)d_in[4];
    const float* fc1_w1 = (const float*)d_in[7];
    const float* fc1_b1 = (const float*)d_in[8];
    const float* fc1_w2 = (const float*)d_in[9];
    const float* fc1_b2 = (const float*)d_in[10];
    const float* fc2_w1 = (const float*)d_in[11];
    const float* fc2_b1 = (const float*)d_in[12];
    const float* fc2_w2 = (const float*)d_in[13];
    const float* fc2_b2 = (const float*)d_in[14];
    float* out = (float*)d_out;

    // A: compute + zero/scatter of row[0..HEAD) — 512 blocks, one wave
    compute_kernel<<<ROWS / 8, 256>>>(tgt, dists, kkf, nsp,
                                      fc1_w1, fc1_b1, fc1_w2, fc1_b2,
                                      fc2_w1, fc2_b1, fc2_w2, fc2_b2,
                                      out);

    // B: flat zero+scatter over [HEAD, VV), grid (15 chunks, 4096 rows)
    dim3 grid(NCHUNK, ROWS);
    zero_scatter_kernel<<<grid, 256>>>(out);
}

// round 17
// speedup vs baseline: 1.0082x; 1.0031x over previous
#include <cuda_runtime.h>
#include <cstdint>

// Problem constants (B=4, S=1024, K=32, V=32000)
#define BB 4
#define SS 1024
#define KK 32
#define VV 32000
#define ROWS (BB * SS)          // 4096
#define HEAD 3328               // floats zeroed by kernel A (26 * 128)
#define CHUNK 4096              // floats per consumer block (4 float4/thread)
#define NCHUNK 7                // (VV - HEAD) / CHUNK == 7 exactly

// Scratch (device global — no allocation). Packed deduped scatter list:
// .x = target index (or -1 for dropped duplicate lanes), .y = float bits of p.
__device__ int2 g_scat[ROWS * KK];

__device__ __forceinline__ float fast_tanh(float x) {
    float r;
    asm("tanh.approx.f32 %0, %1;" : "=f"(r) : "f"(x));
    return r;
}

// ---------------------------------------------------------------------------
// Kernel A: one warp per row, 8 rows/block (512 blocks, one wave).
//   1) 26 fire-and-forget float4 stores zeroing row[0..HEAD)
//   2) combiner chain runs while stores drain (live subgraph only):
//      label_counts (match_any) -> fc2 -> tempe ; log feats -> fc1 -> noise ;
//      p = softmax(-d*tempe + noise); in-warp duplicate-target combine
//   3) __syncwarp, inline-scatter of targets < HEAD into own row
//   4) publish packed (t,p) for the consumer (targets >= HEAD)
// ---------------------------------------------------------------------------
__global__ void __launch_bounds__(256) compute_kernel(
    const int*   __restrict__ tgt,
    const float* __restrict__ dists,
    const float* __restrict__ kkf,
    const float* __restrict__ nsp,
    const float* __restrict__ fc1_w1,  // (2,4)
    const float* __restrict__ fc1_b1,  // (4)
    const float* __restrict__ fc1_w2,  // (4,1)
    const float* __restrict__ fc1_b2,  // (1)
    const float* __restrict__ fc2_w1,  // (64,32)
    const float* __restrict__ fc2_b1,  // (32)
    const float* __restrict__ fc2_w2,  // (32,2)
    const float* __restrict__ fc2_b2,  // (2)
    float*       __restrict__ out)     // (ROWS, VV)
{
    const unsigned FULL = 0xffffffffu;
    __shared__ float feat[8][64];
    __shared__ float sp  [8][32];

    const int w    = threadIdx.x >> 5;
    const int lane = threadIdx.x & 31;
    const int row  = blockIdx.x * 8 + w;
    const int base = row * KK + lane;
    float* rowp = out + (size_t)row * VV;

    // ---- 1) zero row[0..HEAD): 26 independent float4 stores per lane ------
    {
        const float4 z = make_float4(0.f, 0.f, 0.f, 0.f);
        #pragma unroll
        for (int k = 0; k < HEAD / 128; k++) {        // 26 iterations
            *(float4*)(rowp + k * 128 + lane * 4) = z;
        }
    }

    // ---- 2) combiner chain (overlaps the store drain) ----------------------
    int   t   = tgt[base];
    float d   = dists[base];
    float lkf = __logf(kkf[base]);
    float lsp = __logf(nsp[base]);

    // label_counts: distinct nonzero labels in prefix [0..lane]
    unsigned mgrp = __match_any_sync(FULL, t);
    int leader = __ffs(mgrp) - 1;
    bool fo = (t != 0) && (leader == lane);
    unsigned fomask = __ballot_sync(FULL, fo);
    float lc = (float)__popc(fomask & (0xFFFFFFFFu >> (31 - lane)));

    // fc1 -> noise_logit
    float noise = fc1_b2[0];
    #pragma unroll
    for (int m = 0; m < 4; m++) {
        float h = fmaf(lkf, fc1_w1[m], fmaf(lsp, fc1_w1[4 + m], fc1_b1[m]));
        noise = fmaf(fast_tanh(h), fc1_w2[m], noise);
    }

    // stage feats, then fc2: hidden[lane] = b1 + sum_j feat[j]*W1[j][lane]
    feat[w][lane]      = d;
    feat[w][32 + lane] = lc;
    __syncwarp();
    float hid = fc2_b1[lane];
    #pragma unroll
    for (int j = 0; j < 64; j++) {
        hid = fmaf(feat[w][j], fc2_w1[j * 32 + lane], hid);
    }
    float ht = fast_tanh(hid);

    // lambda_logit[1] -> tempe
    float l1 = ht * fc2_w2[lane * 2 + 1];
    #pragma unroll
    for (int off = 16; off; off >>= 1) l1 += __shfl_xor_sync(FULL, l1, off);
    l1 += fc2_b2[1];
    float tempe = 1.f / (1.f + __expf(-l1));

    // softmax over K of (-d*tempe + noise)
    float logit = fmaf(-d, tempe, noise);
    float mx = logit;
    #pragma unroll
    for (int off = 16; off; off >>= 1) mx = fmaxf(mx, __shfl_xor_sync(FULL, mx, off));
    float e = __expf(logit - mx);
    float s = e;
    #pragma unroll
    for (int off = 16; off; off >>= 1) s += __shfl_xor_sync(FULL, s, off);
    float p = e / s;

    // in-warp duplicate-target combine (group-sum via smem)
    sp[w][lane] = p;
    __syncwarp();
    float psum = p;
    unsigned m = mgrp & ~(1u << lane);
    while (m) { int j = __ffs(m) - 1; psum += sp[w][j]; m &= m - 1; }
    int tkeep = (leader == lane) ? t : -1;

    // ---- 3) inline scatter for targets in [0, HEAD) ------------------------
    __syncwarp();   // order this warp's zero stores before the scatter store
    if (tkeep >= 0 && tkeep < HEAD) rowp[tkeep] = psum;

    // ---- 4) publish for the consumer (targets >= HEAD match there) --------
    g_scat[base] = make_int2(tkeep, __float_as_int(psum));
}

// ---------------------------------------------------------------------------
// Kernel B: zero + inline scatter over [HEAD, VV) — uniform CHUNK=4096
// blocks (R15's best per-byte fill shape). Grid (7, 4096); 4 independent
// float4 stores per thread, predicate-free; warp 0 prefetches the packed
// scatter list and plain-stores hits after the barrier.
// ---------------------------------------------------------------------------
__global__ void __launch_bounds__(256) zero_scatter_kernel(
    float* __restrict__ out)
{
    const int row   = blockIdx.y;
    const int chunk = blockIdx.x;
    const int tid   = threadIdx.x;

    const int lo = HEAD + chunk * CHUNK;
    float* rowp = out + (size_t)row * VV + lo;

    // prefetch the packed scatter entry (warp 0) before the stores
    int2 sc = make_int2(-1, 0);
    if (tid < 32) sc = g_scat[row * KK + tid];

    // zero this chunk: four independent float4 stores per thread (no bounds
    // checks needed — chunks are uniform and exactly tile [HEAD, VV))
    const float4 z = make_float4(0.f, 0.f, 0.f, 0.f);
    int i4 = tid * 4;
    #pragma unroll
    for (int k = 0; k < 4; k++) {
        *(float4*)(rowp + i4 + k * 1024) = z;
    }

    __syncthreads();  // order zero-stores before the targeted stores

    if (tid < 32) {
        int loc = sc.x - lo;                    // sc.x < HEAD never matches
        if (loc >= 0 && loc < CHUNK) rowp[loc] = __int_as_float(sc.y);
    }
}

// metadata order:
//  0 tgt_index(i32) 1 knn_dists 2 knn_key_feature 3 network_probs(UNUSED)
//  4 network_select_probs 5 dfc_w(UNUSED) 6 dfc_b(UNUSED)
//  7 fc1_w1 8 fc1_b1 9 fc1_w2 10 fc1_b2 11 fc2_w1 12 fc2_b1 13 fc2_w2 14 fc2_b2
extern "C" void kernel_launch(void* const* d_in, const int* in_sizes, int n_in,
                              void* d_out, int out_size) {
    const int*   tgt    = (const int*)  d_in[0];
    const float* dists  = (const float*)d_in[1];
    const float* kkf    = (const float*)d_in[2];
    const float* nsp    = (const float*)d_in[4];
    const float* fc1_w1 = (const float*)d_in[7];
    const float* fc1_b1 = (const float*)d_in[8];
    const float* fc1_w2 = (const float*)d_in[9];
    const float* fc1_b2 = (const float*)d_in[10];
    const float* fc2_w1 = (const float*)d_in[11];
    const float* fc2_b1 = (const float*)d_in[12];
    const float* fc2_w2 = (const float*)d_in[13];
    const float* fc2_b2 = (const float*)d_in[14];
    float* out = (float*)d_out;

    // A: compute + zero/scatter of row[0..HEAD) — 512 blocks, one wave
    compute_kernel<<<ROWS / 8, 256>>>(tgt, dists, kkf, nsp,
                                      fc1_w1, fc1_b1, fc1_w2, fc1_b2,
                                      fc2_w1, fc2_b1, fc2_w2, fc2_b2,
                                      out);

    // B: flat zero+scatter over [HEAD, VV), grid (7 chunks, 4096 rows)
    dim3 grid(NCHUNK, ROWS);
    zero_scatter_kernel<<<grid, 256>>>(out);
}